// round 13
// baseline (speedup 1.0000x reference)
#include <cuda_runtime.h>
#include <cuda_fp16.h>
#include <cstdint>

// ElementUpdate: out[n,:] = h_prev[n,:] + W[z[n]] @ m_curr[n,:]
// N=16384, D=128, S=119, z sorted.
// R13: prologue converts W -> fp16 device buffer once per call; main kernel
// (R12 skeleton) cp.async's fp16 W with double buffering across sorted-species
// segments, and keeps A fragments in registers across segments. fp16 m16n8k16.

static constexpr int D = 128;
static constexpr int NSPEC = 119;
static constexpr int TILE_M = 64;
static constexpr int NT = 256;
static constexpr int HPAD = 136;               // half stride: 272B row, conflict-free
static constexpr int HDR = 1024;
static constexpr int A_BYTES = TILE_M * HPAD * 2;   // 17408
static constexpr int W_BYTES = D * HPAD * 2;        // 34816 per buffer
static constexpr int SMEM_BYTES = HDR + A_BYTES + 2 * W_BYTES;  // 87040 -> 2 CTAs/SM

__device__ __half g_wh[NSPEC * D * D];   // fp16 weights (prologue output)

__device__ __forceinline__ uint32_t pack_h2(float lo, float hi) {
    uint32_t r;
    asm("cvt.rn.f16x2.f32 %0, %1, %2;" : "=r"(r) : "f"(hi), "f"(lo));
    return r;
}

__device__ __forceinline__ uint32_t smem_u32(const void* p) {
    uint32_t a;
    asm("{ .reg .u64 t; cvta.to.shared.u64 t, %1; cvt.u32.u64 %0, t; }" : "=r"(a) : "l"(p));
    return a;
}

__device__ __forceinline__ void cpa16(uint32_t dst, const void* src) {
    asm volatile("cp.async.cg.shared.global [%0], [%1], 16;" :: "r"(dst), "l"(src));
}
#define CP_COMMIT() asm volatile("cp.async.commit_group;" ::: "memory")
#define CP_WAIT(n)  asm volatile("cp.async.wait_group %0;" :: "n"(n) : "memory")

__device__ __forceinline__ void mma_f16(float* d, const uint32_t* a,
                                        uint32_t b0, uint32_t b1) {
    asm volatile(
        "mma.sync.aligned.m16n8k16.row.col.f32.f16.f16.f32 "
        "{%0,%1,%2,%3}, {%4,%5,%6,%7}, {%8,%9}, {%0,%1,%2,%3};"
        : "+f"(d[0]), "+f"(d[1]), "+f"(d[2]), "+f"(d[3])
        : "r"(a[0]), "r"(a[1]), "r"(a[2]), "r"(a[3]), "r"(b0), "r"(b1));
}

// ---------------- prologue: weight fp32 -> fp16 ----------------
__global__ void __launch_bounds__(NT, 4) convert_w(const float* __restrict__ w) {
    int i = blockIdx.x * NT + threadIdx.x;            // over float4 chunks
    float4 v = ((const float4*)w)[i];
    uint2 u;
    u.x = pack_h2(v.x, v.y);
    u.y = pack_h2(v.z, v.w);
    ((uint2*)g_wh)[i] = u;
}

// ---------------- main ----------------
__global__ void __launch_bounds__(NT, 2)
element_update_kernel(const float* __restrict__ h_prev,
                      const float* __restrict__ m_curr,
                      const int* __restrict__ atom_types,
                      float* __restrict__ out) {
    extern __shared__ __align__(16) char smem[];
    const int tid = threadIdx.x;
    const int lane = tid & 31;
    const int wid = tid >> 5;
    const int R0 = blockIdx.x * TILE_M;

    int* sCnt  = (int*)(smem + 0);
    int* sNseg = (int*)(smem + 32);
    int* sRow  = (int*)(smem + 64);     // up to TILE_M+1
    int* sSpec = (int*)(smem + 384);    // up to TILE_M
    __half* sA = (__half*)(smem + HDR);
    __half* sW0 = (__half*)(smem + HDR + A_BYTES);
    __half* sW1 = (__half*)(smem + HDR + A_BYTES + W_BYTES);
    __half* sWb[2] = {sW0, sW1};

    const uint32_t sbase = smem_u32(smem);
    const uint32_t wU[2] = {sbase + HDR + A_BYTES, sbase + HDR + A_BYTES + W_BYTES};

    // cp.async job: fp16 W[s] (full 128x128) -> buffer b. 8 x 16B per thread.
    auto issue_w = [&](int s, int b) {
        const __half* src = g_wh + (size_t)s * (D * D);
        uint32_t dU = wU[b];
        #pragma unroll
        for (int j = 0; j < 8; j++) {
            int i = tid + j * NT;
            int r = i >> 4, c8 = (i & 15) << 3;            // 16 chunks per 128-half row
            cpa16(dU + (uint32_t)(r * HPAD + c8) * 2u, src + r * D + c8);
        }
        CP_COMMIT();
    };

    // ---- W[s0] prefetch starts immediately ----
    const int s0 = atom_types[R0];
    issue_w(s0, 0);

    // ---- species-segment scan over TILE_M sorted z values (warps 0-1) ----
    bool bd = false; int wpre = 0, zr = 0;
    if (tid < TILE_M) {
        zr = atom_types[R0 + tid];
        int zp = (tid == 0) ? -1 : atom_types[R0 + tid - 1];
        bd = (zp != zr);
        unsigned msk = __ballot_sync(0xffffffffu, bd);
        wpre = __popc(msk & ((1u << lane) - 1u));
        if (lane == 0) sCnt[wid] = __popc(msk);
    }

    // ---- A fill (m_curr fp32 -> fp16 smem), overlapped with W0 prefetch ----
    #pragma unroll
    for (int j = 0; j < 8; j++) {
        int i = tid + j * NT;
        int r = i >> 5, c4 = (i & 31) << 2;
        float4 v = *(const float4*)(m_curr + (size_t)(R0 + r) * D + c4);
        uint2 u;
        u.x = pack_h2(v.x, v.y);
        u.y = pack_h2(v.z, v.w);
        *(uint2*)(sA + r * HPAD + c4) = u;
    }
    __syncthreads();
    if (tid == 0) {
        int c0 = sCnt[0], c1 = sCnt[1];
        sCnt[2] = c0;
        *sNseg = c0 + c1;
        sRow[c0 + c1] = TILE_M;
    }
    __syncthreads();
    if (tid < TILE_M && bd) {
        int i = (wid ? sCnt[2] : 0) + wpre;
        sRow[i] = tid;
        sSpec[i] = zr;
    }
    __syncthreads();
    const int nseg = *sNseg;

    // ---- issue W1 prefetch (if any), then wait for W0 ----
    if (nseg > 1) { issue_w(sSpec[1], 1); CP_WAIT(1); }
    else          { CP_WAIT(0); }
    __syncthreads();       // A + W0 visible to all

    // ---- warp geometry: rows [16*wr,+16) x cols [64*wc,+64) ----
    const int wr = wid >> 1;     // 0..3
    const int wc = wid & 1;      // 0..1
    const int rlo = wr * 16;
    const int lr = lane >> 2;    // 0..7
    const int lc = lane & 3;     // 0..3

    // ---- preload ALL A fragments into registers (constant across segments) ----
    uint32_t aR[8][4];
    {
        const __half* pA0 = sA + (rlo + lr) * HPAD + lc * 2;
        const __half* pA1 = pA0 + 8 * HPAD;
        #pragma unroll
        for (int ks = 0; ks < 8; ks++) {
            const int k0 = ks * 16;
            aR[ks][0] = *(const uint32_t*)(pA0 + k0);
            aR[ks][1] = *(const uint32_t*)(pA1 + k0);
            aR[ks][2] = *(const uint32_t*)(pA0 + k0 + 8);
            aR[ks][3] = *(const uint32_t*)(pA1 + k0 + 8);
        }
    }

    float acc[8][4];
    #pragma unroll
    for (int nt = 0; nt < 8; nt++)
        #pragma unroll
        for (int j = 0; j < 4; j++) acc[nt][j] = 0.f;

    for (int seg = 0; seg < nseg; seg++) {
        const int a = sRow[seg];
        const int b = sRow[seg + 1];
        const __half* pB0 = sWb[seg & 1] + (wc * 64 + lr) * HPAD + lc * 2;

        if (b > rlo && a < rlo + 16) {
            const int r0 = rlo + lr;
            const uint32_t am0 = (r0 >= a && r0 < b) ? 0xffffffffu : 0u;
            const uint32_t am1 = (r0 + 8 >= a && r0 + 8 < b) ? 0xffffffffu : 0u;

            #pragma unroll
            for (int ks = 0; ks < 8; ks++) {
                const int k0 = ks * 16;
                uint32_t aF[4];
                aF[0] = aR[ks][0] & am0;
                aF[1] = aR[ks][1] & am1;
                aF[2] = aR[ks][2] & am0;
                aF[3] = aR[ks][3] & am1;
                #pragma unroll
                for (int nt = 0; nt < 8; nt++) {
                    const __half* pB = pB0 + nt * (8 * HPAD) + k0;
                    uint32_t b0 = *(const uint32_t*)(pB);
                    uint32_t b1 = *(const uint32_t*)(pB + 8);
                    mma_f16(acc[nt], aF, b0, b1);
                }
            }
        }

        if (seg + 1 < nseg) {
            __syncthreads();                       // readers done with buf (seg&1)
            if (seg + 2 < nseg) { issue_w(sSpec[seg + 2], seg & 1); CP_WAIT(1); }
            else                { CP_WAIT(0); }
            __syncthreads();                       // next buffer visible
        }
    }

    // ---- epilogue: acc + h_prev -> out (coalesced float2, 32B sectors) ----
    #pragma unroll
    for (int h = 0; h < 2; h++) {
        const int r = R0 + rlo + 8 * h + lr;
        const float* hp = h_prev + (size_t)r * D;
        float* op = out + (size_t)r * D;
        #pragma unroll
        for (int nt = 0; nt < 8; nt++) {
            const int c = wc * 64 + 8 * nt + lc * 2;
            float2 hv = *(const float2*)(hp + c);
            float2 o;
            o.x = hv.x + acc[nt][2 * h + 0];
            o.y = hv.y + acc[nt][2 * h + 1];
            *(float2*)(op + c) = o;
        }
    }
}

extern "C" void kernel_launch(void* const* d_in, const int* in_sizes, int n_in,
                              void* d_out, int out_size) {
    const float* h_prev     = (const float*)d_in[0];
    const float* m_curr     = (const float*)d_in[1];
    const int*   atom_types = (const int*)d_in[2];
    const float* weight     = (const float*)d_in[3];
    float* out = (float*)d_out;

    int n_nodes = in_sizes[0] / D;       // 16384
    int grid = n_nodes / TILE_M;         // 256
    int wchunks = (NSPEC * D * D) / 4;   // float4 chunks
    int wgrid = wchunks / NT;            // 1904 (exact: 487424/256)

    cudaFuncSetAttribute(element_update_kernel,
                         cudaFuncAttributeMaxDynamicSharedMemorySize, SMEM_BYTES);

    convert_w<<<wgrid, NT>>>(weight);
    element_update_kernel<<<grid, NT, SMEM_BYTES>>>(h_prev, m_curr, atom_types, out);
}